// round 1
// baseline (speedup 1.0000x reference)
#include <cuda_runtime.h>
#include <math.h>

#define B_    16
#define T_    512
#define FEAT_ 40
#define DM    256
#define DI    512
#define DS    16
#define DR    16
#define NL    8
#define NTOK  (B_*T_)
#define NCLS  35

// ---------------- scratch (device globals: allocation-free) ----------------
__device__ __align__(16) float g_h  [NTOK*DM];     // residual stream
__device__ __align__(16) float g_xln[NTOK*DM];     // layernormed input
__device__ __align__(16) float g_xz [NTOK*2*DI];   // in-proj output (u|z)
__device__ __align__(16) float g_u  [NTOK*DI];     // conv+silu output
__device__ __align__(16) float g_dbl[NTOK*48];     // x-proj output (dt_lr|B|C)
__device__ __align__(16) float g_dt [NTOK*DI];     // softplus dt
__device__ __align__(16) float g_y  [NTOK*DI];     // scan output
__device__ __align__(16) float g_yg [NTOK*DI];     // y * silu(z)
__device__ __align__(16) float g_pool[B_*DM];

__device__ __forceinline__ float silu_f(float x){ return x / (1.f + __expf(-x)); }

// ---------------- input projection + LN + silu ----------------
__global__ void k_inproj(const float* __restrict__ x, const float* __restrict__ pw,
                         const float* __restrict__ pb, const float* __restrict__ g,
                         const float* __restrict__ bb){
    int tok = blockIdx.x, tid = threadIdx.x;
    __shared__ float xs[FEAT_];
    __shared__ float ss[DM], sq[DM];
    if (tid < FEAT_) xs[tid] = x[tok*FEAT_ + tid];
    __syncthreads();
    float acc = pb[tid];
    #pragma unroll
    for (int f = 0; f < FEAT_; f++) acc += xs[f] * pw[tid*FEAT_ + f];
    ss[tid] = acc; sq[tid] = acc*acc; __syncthreads();
    for (int st = DM/2; st > 0; st >>= 1){
        if (tid < st){ ss[tid] += ss[tid+st]; sq[tid] += sq[tid+st]; }
        __syncthreads();
    }
    float m   = ss[0] * (1.f/DM);
    float var = sq[0] * (1.f/DM) - m*m;
    float r   = rsqrtf(var + 1e-5f);
    float v   = (acc - m) * r * g[tid] + bb[tid];
    g_h[tok*DM + tid] = silu_f(v);
}

// ---------------- layernorm of g_h -> g_xln ----------------
__global__ void k_ln(const float* __restrict__ g, const float* __restrict__ bb){
    int tok = blockIdx.x, tid = threadIdx.x;
    __shared__ float ss[DM], sq[DM];
    float v = g_h[tok*DM + tid];
    ss[tid] = v; sq[tid] = v*v; __syncthreads();
    for (int st = DM/2; st > 0; st >>= 1){
        if (tid < st){ ss[tid] += ss[tid+st]; sq[tid] += sq[tid+st]; }
        __syncthreads();
    }
    float m   = ss[0] * (1.f/DM);
    float var = sq[0] * (1.f/DM) - m*m;
    float r   = rsqrtf(var + 1e-5f);
    g_xln[tok*DM + tid] = (v - m) * r * g[tid] + bb[tid];
}

// ---------------- SGEMM: C[M,N] = A[M,K] @ W[N,K]^T (optional accumulate) ----
// BM=BN=64, BK=16, 256 threads, 4x4 micro-tile
__global__ void sgemm_tn(const float* __restrict__ A, const float* __restrict__ W,
                         float* __restrict__ C, int M, int N, int K, int accum){
    __shared__ float As[16][68];
    __shared__ float Ws[16][68];
    int tid = threadIdx.x;
    int tx = tid & 15, ty = tid >> 4;
    int bm = blockIdx.y * 64, bn = blockIdx.x * 64;
    int lrow = tid >> 2, lk = (tid & 3) * 4;
    const float* Ap = A + (size_t)(bm + lrow) * K + lk;
    const float* Wp = W + (size_t)(bn + lrow) * K + lk;
    float acc[4][4] = {};
    for (int k0 = 0; k0 < K; k0 += 16){
        float4 a = *(const float4*)(Ap + k0);
        float4 w = *(const float4*)(Wp + k0);
        As[lk+0][lrow] = a.x; As[lk+1][lrow] = a.y; As[lk+2][lrow] = a.z; As[lk+3][lrow] = a.w;
        Ws[lk+0][lrow] = w.x; Ws[lk+1][lrow] = w.y; Ws[lk+2][lrow] = w.z; Ws[lk+3][lrow] = w.w;
        __syncthreads();
        #pragma unroll
        for (int k = 0; k < 16; k++){
            float4 af = *(const float4*)&As[k][ty*4];
            float4 wf = *(const float4*)&Ws[k][tx*4];
            float av[4] = {af.x, af.y, af.z, af.w};
            float wv[4] = {wf.x, wf.y, wf.z, wf.w};
            #pragma unroll
            for (int i = 0; i < 4; i++)
                #pragma unroll
                for (int j = 0; j < 4; j++)
                    acc[i][j] = fmaf(av[i], wv[j], acc[i][j]);
        }
        __syncthreads();
    }
    #pragma unroll
    for (int i = 0; i < 4; i++){
        float* cp = C + (size_t)(bm + ty*4 + i) * N + bn + tx*4;
        float4 cv;
        if (accum){
            cv = *(const float4*)cp;
            cv.x += acc[i][0]; cv.y += acc[i][1]; cv.z += acc[i][2]; cv.w += acc[i][3];
        } else {
            cv.x = acc[i][0]; cv.y = acc[i][1]; cv.z = acc[i][2]; cv.w = acc[i][3];
        }
        *(float4*)cp = cv;
    }
}

// ---------------- causal depthwise conv (k=4) + silu on u half of xz --------
__global__ void k_conv(const float* __restrict__ cw, const float* __restrict__ cb){
    int idx = blockIdx.x * blockDim.x + threadIdx.x;   // < NTOK*DI
    int d = idx & (DI-1);
    int t = (idx >> 9) & (T_-1);
    int b = idx >> 18;
    const float* base = g_xz + (size_t)b * T_ * 2 * DI + d;
    float acc = cb[d];
    #pragma unroll
    for (int j = 0; j < 4; j++){
        int tt = t - 3 + j;
        if (tt >= 0) acc = fmaf(cw[d*4 + j], base[(size_t)tt * 2 * DI], acc);
    }
    g_u[idx] = silu_f(acc);
}

// ---------------- x-proj (48 outputs) + dt-proj + softplus -----------------
__global__ void k_xpdt(const float* __restrict__ xpw, const float* __restrict__ dtw,
                       const float* __restrict__ dtb){
    int tok = blockIdx.x, tid = threadIdx.x;  // 512 threads
    __shared__ float us[DI];
    __shared__ float part[48*8];
    __shared__ float dbls[48];
    us[tid] = g_u[(size_t)tok*DI + tid];
    __syncthreads();
    if (tid < 384){
        int j = tid >> 3, p = tid & 7;
        const float* wp = xpw + j*DI + p*64;
        const float* up = us + p*64;
        float a = 0.f;
        #pragma unroll
        for (int k = 0; k < 64; k++) a = fmaf(up[k], wp[k], a);
        part[tid] = a;
    }
    __syncthreads();
    if (tid < 48){
        float s = 0.f;
        #pragma unroll
        for (int p = 0; p < 8; p++) s += part[tid*8 + p];
        dbls[tid] = s;
        g_dbl[(size_t)tok*48 + tid] = s;
    }
    __syncthreads();
    float a = dtb[tid];
    #pragma unroll
    for (int r = 0; r < 16; r++) a = fmaf(dbls[r], dtw[tid*16 + r], a);
    float sp = (a > 20.f) ? a : log1pf(__expf(a));
    g_dt[(size_t)tok*DI + tid] = sp;
}

// ---------------- selective scan: warp = 2 channels x 16 states ------------
__global__ void k_scan(const float* __restrict__ Alog, const float* __restrict__ Dp){
    int w    = blockIdx.x * 8 + (threadIdx.x >> 5);  // 4096 warps total
    int lane = threadIdx.x & 31;
    int b    = w >> 8;
    int pair = w & 255;
    int ch   = pair*2 + (lane >> 4);
    int s    = lane & 15;
    float A  = -__expf(Alog[ch*DS + s]);
    float Dd = Dp[ch];
    float h  = 0.f;
    const float* dblp = g_dbl + (size_t)b*T_*48 + 16;
    const float* dtp  = g_dt  + (size_t)b*T_*DI + ch;
    const float* up   = g_u   + (size_t)b*T_*DI + ch;
    float*       yp   = g_y   + (size_t)b*T_*DI + ch;
    for (int t = 0; t < T_; t++){
        float v   = dblp[t*48 + lane];                       // one coalesced LDG: B|C
        float Bs  = __shfl_sync(0xffffffffu, v, s);
        float Cs  = __shfl_sync(0xffffffffu, v, s + 16);
        float dtv = dtp[(size_t)t*DI];
        float uv  = up[(size_t)t*DI];
        float dA  = __expf(dtv * A);
        h = fmaf(h, dA, (dtv*uv)*Bs);
        float p = h * Cs;
        p += __shfl_xor_sync(0xffffffffu, p, 1);
        p += __shfl_xor_sync(0xffffffffu, p, 2);
        p += __shfl_xor_sync(0xffffffffu, p, 4);
        p += __shfl_xor_sync(0xffffffffu, p, 8);
        if (s == 0) yp[(size_t)t*DI] = fmaf(uv, Dd, p);
    }
}

// ---------------- gating: yg = y * silu(z) ----------------
__global__ void k_ygate(){
    int idx = blockIdx.x * blockDim.x + threadIdx.x;  // < NTOK*DI
    int d   = idx & (DI-1);
    int tok = idx >> 9;
    float z = g_xz[(size_t)tok*2*DI + DI + d];
    g_yg[idx] = g_y[idx] * silu_f(z);
}

// ---------------- masked mean pool over time ----------------
__global__ void k_pool(const int* __restrict__ lengths){
    int b = blockIdx.x, tid = threadIdx.x;   // 256 threads
    int len = lengths[b];
    if (len < 1) len = 1;
    const float* p = g_xln + (size_t)b*T_*DM + tid;
    float s = 0.f;
    for (int t = 0; t < len; t++) s += p[(size_t)t*DM];
    g_pool[b*DM + tid] = s / (float)len;
}

// ---------------- classifier head ----------------
__global__ void k_head(const float* __restrict__ c1w, const float* __restrict__ c1b,
                       const float* __restrict__ c2w, const float* __restrict__ c2b,
                       float* __restrict__ out){
    int b = blockIdx.x, tid = threadIdx.x;   // 128 threads
    __shared__ float ps[DM];
    __shared__ float z1[DM/2];
    ps[tid]       = g_pool[b*DM + tid];
    ps[tid + 128] = g_pool[b*DM + tid + 128];
    __syncthreads();
    float a = c1b[tid];
    #pragma unroll 4
    for (int k = 0; k < DM; k++) a = fmaf(ps[k], c1w[tid*DM + k], a);
    z1[tid] = silu_f(a);
    __syncthreads();
    if (tid < NCLS){
        float o = c2b[tid];
        #pragma unroll 4
        for (int k = 0; k < 128; k++) o = fmaf(z1[k], c2w[tid*128 + k], o);
        out[b*NCLS + tid] = o;
    }
}

// ---------------- host launch ----------------
extern "C" void kernel_launch(void* const* d_in, const int* in_sizes, int n_in,
                              void* d_out, int out_size){
    const float* x      = (const float*)d_in[0];
    const int*   lens   = (const int*)  d_in[1];
    const float* proj_w = (const float*)d_in[2];
    const float* proj_b = (const float*)d_in[3];
    const float* pln_g  = (const float*)d_in[4];
    const float* pln_b  = (const float*)d_in[5];
    const float* ln_g   = (const float*)d_in[6];
    const float* ln_b   = (const float*)d_in[7];
    const float* in_w   = (const float*)d_in[8];
    const float* conv_w = (const float*)d_in[9];
    const float* conv_b = (const float*)d_in[10];
    const float* xp_w   = (const float*)d_in[11];
    const float* dt_w   = (const float*)d_in[12];
    const float* dt_b   = (const float*)d_in[13];
    const float* A_log  = (const float*)d_in[14];
    const float* Dp     = (const float*)d_in[15];
    const float* out_w  = (const float*)d_in[16];
    const float* pre_g  = (const float*)d_in[17];
    const float* pre_b  = (const float*)d_in[18];
    const float* c1_w   = (const float*)d_in[19];
    const float* c1_b   = (const float*)d_in[20];
    const float* c2_w   = (const float*)d_in[21];
    const float* c2_b   = (const float*)d_in[22];
    float* out = (float*)d_out;

    float *p_xln, *p_xz, *p_yg, *p_h;
    cudaGetSymbolAddress((void**)&p_xln, g_xln);
    cudaGetSymbolAddress((void**)&p_xz,  g_xz);
    cudaGetSymbolAddress((void**)&p_yg,  g_yg);
    cudaGetSymbolAddress((void**)&p_h,   g_h);

    k_inproj<<<NTOK, DM>>>(x, proj_w, proj_b, pln_g, pln_b);

    for (int i = 0; i < NL; i++){
        k_ln<<<NTOK, DM>>>(ln_g + i*DM, ln_b + i*DM);

        dim3 gin(2*DI/64, NTOK/64);       // (16, 128)
        sgemm_tn<<<gin, 256>>>(p_xln, in_w + (size_t)i*2*DI*DM, p_xz,
                               NTOK, 2*DI, DM, 0);

        k_conv<<<NTOK*DI/256, 256>>>(conv_w + i*DI*4, conv_b + i*DI);

        k_xpdt<<<NTOK, DI>>>(xp_w + (size_t)i*48*DI,
                             dt_w + (size_t)i*DI*DR,
                             dt_b + i*DI);

        k_scan<<<512, 256>>>(A_log + (size_t)i*DI*DS, Dp + i*DI);

        k_ygate<<<NTOK*DI/256, 256>>>();

        dim3 gout(DM/64, NTOK/64);        // (4, 128)
        sgemm_tn<<<gout, 256>>>(p_yg, out_w + (size_t)i*DM*DI, p_h,
                                NTOK, DM, DI, 1);
    }

    k_ln<<<NTOK, DM>>>(pre_g, pre_b);
    k_pool<<<B_, DM>>>(lens);
    k_head<<<B_, 128>>>(c1_w, c1_b, c2_w, c2_b, out);
}

// round 2
// speedup vs baseline: 2.5047x; 2.5047x over previous
#include <cuda_runtime.h>
#include <math.h>

#define B_    16
#define T_    512
#define FEAT_ 40
#define DM    256
#define DI    512
#define DS    16
#define DR    16
#define NL    8
#define NTOK  (B_*T_)
#define NCLS  35

// ---------------- scratch (device globals: allocation-free) ----------------
__device__ __align__(16) float g_h  [NTOK*DM];     // residual stream
__device__ __align__(16) float g_xln[NTOK*DM];     // layernormed input
__device__ __align__(16) float g_xz [NTOK*2*DI];   // in-proj output (u|z)
__device__ __align__(16) float g_u  [NTOK*DI];     // conv+silu output
__device__ __align__(16) float g_dbl[NTOK*48];     // x-proj output (dt_lr|B|C)
__device__ __align__(16) float g_dt [NTOK*DI];     // softplus dt
__device__ __align__(16) float g_y  [NTOK*DI];     // scan output
__device__ __align__(16) float g_pool[B_*DM];

__device__ __forceinline__ float silu_f(float x){ return x / (1.f + __expf(-x)); }

// ---------------- input projection + LN + silu ----------------
__global__ void k_inproj(const float* __restrict__ x, const float* __restrict__ pw,
                         const float* __restrict__ pb, const float* __restrict__ g,
                         const float* __restrict__ bb){
    int tok = blockIdx.x, tid = threadIdx.x;
    __shared__ float xs[FEAT_];
    __shared__ float ss[DM], sq[DM];
    if (tid < FEAT_) xs[tid] = x[tok*FEAT_ + tid];
    __syncthreads();
    float acc = pb[tid];
    #pragma unroll
    for (int f = 0; f < FEAT_; f++) acc += xs[f] * pw[tid*FEAT_ + f];
    ss[tid] = acc; sq[tid] = acc*acc; __syncthreads();
    for (int st = DM/2; st > 0; st >>= 1){
        if (tid < st){ ss[tid] += ss[tid+st]; sq[tid] += sq[tid+st]; }
        __syncthreads();
    }
    float m   = ss[0] * (1.f/DM);
    float var = sq[0] * (1.f/DM) - m*m;
    float r   = rsqrtf(var + 1e-5f);
    float v   = (acc - m) * r * g[tid] + bb[tid];
    g_h[tok*DM + tid] = silu_f(v);
}

// ---------------- layernorm of g_h -> g_xln ----------------
__global__ void k_ln(const float* __restrict__ g, const float* __restrict__ bb){
    int tok = blockIdx.x, tid = threadIdx.x;
    __shared__ float ss[DM], sq[DM];
    float v = g_h[tok*DM + tid];
    ss[tid] = v; sq[tid] = v*v; __syncthreads();
    for (int st = DM/2; st > 0; st >>= 1){
        if (tid < st){ ss[tid] += ss[tid+st]; sq[tid] += sq[tid+st]; }
        __syncthreads();
    }
    float m   = ss[0] * (1.f/DM);
    float var = sq[0] * (1.f/DM) - m*m;
    float r   = rsqrtf(var + 1e-5f);
    g_xln[tok*DM + tid] = (v - m) * r * g[tid] + bb[tid];
}

// ---------------- SGEMM v2: C[M,N] (+)= A[M,K] @ W[N,K]^T ------------------
// BM=128, BN=64, BK=16, 256 threads, 8x4 micro-tile, double-buffered.
// GATE: A[m][k] = A[m][k] * silu(Z[m*2K + K + k])   (fused y*silu(z))
// ACC:  C += result (residual add)
template<int GATE, int ACC>
__global__ void __launch_bounds__(256)
sgemm2(const float* __restrict__ A, const float* __restrict__ Z,
       const float* __restrict__ W, float* __restrict__ C,
       int M, int N, int K){
    __shared__ float As[2][16][132];
    __shared__ float Ws[2][16][68];
    const int tid  = threadIdx.x;
    const int bm   = blockIdx.y * 128, bn = blockIdx.x * 64;
    const int akq  = (tid & 3) * 4;
    const int ar0  = tid >> 2;            // 0..63
    const int ty   = tid >> 4, tx = tid & 15;

    const float* Ap0 = A + (size_t)(bm + ar0)      * K + akq;
    const float* Ap1 = A + (size_t)(bm + ar0 + 64) * K + akq;
    const float* Zp0 = Z + (size_t)(bm + ar0)      * (2*K) + K + akq;
    const float* Zp1 = Z + (size_t)(bm + ar0 + 64) * (2*K) + K + akq;
    const float* Wp  = W + (size_t)(bn + ar0) * K + akq;

    float acc[8][4] = {};
    const int KT = K >> 4;

    float4 a0 = *(const float4*)Ap0;
    float4 a1 = *(const float4*)Ap1;
    float4 w0 = *(const float4*)Wp;
    if (GATE){
        float4 z0 = *(const float4*)Zp0, z1 = *(const float4*)Zp1;
        a0.x *= silu_f(z0.x); a0.y *= silu_f(z0.y); a0.z *= silu_f(z0.z); a0.w *= silu_f(z0.w);
        a1.x *= silu_f(z1.x); a1.y *= silu_f(z1.y); a1.z *= silu_f(z1.z); a1.w *= silu_f(z1.w);
    }
    int buf = 0;
    As[0][akq+0][ar0]    = a0.x; As[0][akq+1][ar0]    = a0.y; As[0][akq+2][ar0]    = a0.z; As[0][akq+3][ar0]    = a0.w;
    As[0][akq+0][ar0+64] = a1.x; As[0][akq+1][ar0+64] = a1.y; As[0][akq+2][ar0+64] = a1.z; As[0][akq+3][ar0+64] = a1.w;
    Ws[0][akq+0][ar0]    = w0.x; Ws[0][akq+1][ar0]    = w0.y; Ws[0][akq+2][ar0]    = w0.z; Ws[0][akq+3][ar0]    = w0.w;
    __syncthreads();

    for (int kt = 0; kt < KT; kt++){
        if (kt + 1 < KT){
            int k0 = (kt + 1) << 4;
            a0 = *(const float4*)(Ap0 + k0);
            a1 = *(const float4*)(Ap1 + k0);
            w0 = *(const float4*)(Wp  + k0);
            if (GATE){
                float4 z0 = *(const float4*)(Zp0 + k0), z1 = *(const float4*)(Zp1 + k0);
                a0.x *= silu_f(z0.x); a0.y *= silu_f(z0.y); a0.z *= silu_f(z0.z); a0.w *= silu_f(z0.w);
                a1.x *= silu_f(z1.x); a1.y *= silu_f(z1.y); a1.z *= silu_f(z1.z); a1.w *= silu_f(z1.w);
            }
        }
        #pragma unroll
        for (int k = 0; k < 16; k++){
            float4 x0 = *(const float4*)&As[buf][k][ty*8];
            float4 x1 = *(const float4*)&As[buf][k][ty*8 + 4];
            float4 wv = *(const float4*)&Ws[buf][k][tx*4];
            float av[8] = {x0.x,x0.y,x0.z,x0.w,x1.x,x1.y,x1.z,x1.w};
            float wf[4] = {wv.x,wv.y,wv.z,wv.w};
            #pragma unroll
            for (int i = 0; i < 8; i++)
                #pragma unroll
                for (int j = 0; j < 4; j++)
                    acc[i][j] = fmaf(av[i], wf[j], acc[i][j]);
        }
        if (kt + 1 < KT){
            buf ^= 1;
            As[buf][akq+0][ar0]    = a0.x; As[buf][akq+1][ar0]    = a0.y; As[buf][akq+2][ar0]    = a0.z; As[buf][akq+3][ar0]    = a0.w;
            As[buf][akq+0][ar0+64] = a1.x; As[buf][akq+1][ar0+64] = a1.y; As[buf][akq+2][ar0+64] = a1.z; As[buf][akq+3][ar0+64] = a1.w;
            Ws[buf][akq+0][ar0]    = w0.x; Ws[buf][akq+1][ar0]    = w0.y; Ws[buf][akq+2][ar0]    = w0.z; Ws[buf][akq+3][ar0]    = w0.w;
            __syncthreads();
        }
    }
    #pragma unroll
    for (int i = 0; i < 8; i++){
        float* cp = C + (size_t)(bm + ty*8 + i) * N + bn + tx*4;
        float4 cv;
        if (ACC){
            cv = *(const float4*)cp;
            cv.x += acc[i][0]; cv.y += acc[i][1]; cv.z += acc[i][2]; cv.w += acc[i][3];
        } else {
            cv.x = acc[i][0]; cv.y = acc[i][1]; cv.z = acc[i][2]; cv.w = acc[i][3];
        }
        *(float4*)cp = cv;
    }
}

// ---------------- causal depthwise conv (k=4) + silu, 4 t per thread -------
__global__ void k_conv2(const float* __restrict__ cw, const float* __restrict__ cb){
    int idx = blockIdx.x * blockDim.x + threadIdx.x;  // < NTOK*DI/4
    int d  = idx & (DI-1);
    int q  = (idx >> 9) & (T_/4 - 1);
    int b  = idx >> 16;
    int t0 = q * 4;
    const float* base = g_xz + (size_t)b * T_ * 2*DI + d;
    float w0 = cw[d*4+0], w1 = cw[d*4+1], w2 = cw[d*4+2], w3 = cw[d*4+3];
    float bias = cb[d];
    float xv[7];
    #pragma unroll
    for (int j = 0; j < 7; j++){
        int tt = t0 - 3 + j;
        xv[j] = (tt >= 0) ? base[(size_t)tt * 2*DI] : 0.f;
    }
    float* op = g_u + ((size_t)b * T_ + t0) * DI + d;
    #pragma unroll
    for (int i = 0; i < 4; i++){
        float a = bias + w0*xv[i] + w1*xv[i+1] + w2*xv[i+2] + w3*xv[i+3];
        op[(size_t)i * DI] = silu_f(a);
    }
}

// ---------------- x-proj + dt-proj + softplus, 16 tokens per block ---------
__global__ void __launch_bounds__(256)
k_xpdt2(const float* __restrict__ xpw, const float* __restrict__ dtw,
        const float* __restrict__ dtb){
    __shared__ float us[16][516];
    __shared__ float dbls[16][48];
    const int tid  = threadIdx.x;
    const int tok0 = blockIdx.x * 16;

    // stage u[16][512] into smem (coalesced float4)
    #pragma unroll
    for (int i = 0; i < 8; i++){
        int idx = i*256 + tid;          // 0..2047
        int tok = idx >> 7;
        int k   = (idx & 127) * 4;
        float4 v = *(const float4*)(g_u + (size_t)(tok0 + tok)*DI + k);
        *(float4*)&us[tok][k] = v;
    }
    __syncthreads();

    // dbl[16][48] = u @ xp_w^T : 768 dot products, 3 per thread
    #pragma unroll
    for (int r = 0; r < 3; r++){
        int idx = r*256 + tid;          // 0..767
        int j   = idx % 48;
        int tok = idx / 48;
        const float* wp = xpw + (size_t)j * DI;
        float a = 0.f;
        #pragma unroll 8
        for (int k = 0; k < DI; k += 4){
            float4 w = *(const float4*)(wp + k);
            float4 u = *(const float4*)&us[tok][k];
            a = fmaf(u.x, w.x, a); a = fmaf(u.y, w.y, a);
            a = fmaf(u.z, w.z, a); a = fmaf(u.w, w.w, a);
        }
        dbls[tok][j] = a;
        g_dbl[(size_t)(tok0 + tok)*48 + j] = a;
    }
    __syncthreads();

    // dt[16][512] = softplus(dbl[:, :16] @ dt_w^T + dt_b)
    #pragma unroll 2
    for (int rep = 0; rep < 32; rep++){
        int idx = rep*256 + tid;        // 0..8191
        int d   = idx & (DI-1);
        int tok = idx >> 9;
        const float* wp = dtw + (size_t)d * DR;
        float a = dtb[d];
        #pragma unroll
        for (int rr = 0; rr < 16; rr += 4){
            float4 w = *(const float4*)(wp + rr);
            float4 x = *(const float4*)&dbls[tok][rr];
            a = fmaf(x.x, w.x, a); a = fmaf(x.y, w.y, a);
            a = fmaf(x.z, w.z, a); a = fmaf(x.w, w.w, a);
        }
        float sp = (a > 20.f) ? a : log1pf(__expf(a));
        g_dt[(size_t)(tok0 + tok)*DI + d] = sp;
    }
}

// ---------------- selective scan: warp = 2 channels x 16 states ------------
__global__ void k_scan(const float* __restrict__ Alog, const float* __restrict__ Dp){
    int w    = blockIdx.x * 8 + (threadIdx.x >> 5);  // 4096 warps total
    int lane = threadIdx.x & 31;
    int b    = w >> 8;
    int pair = w & 255;
    int ch   = pair*2 + (lane >> 4);
    int s    = lane & 15;
    float A  = -__expf(Alog[ch*DS + s]);
    float Dd = Dp[ch];
    float h  = 0.f;
    const float* dblp = g_dbl + (size_t)b*T_*48 + 16;
    const float* dtp  = g_dt  + (size_t)b*T_*DI + ch;
    const float* up   = g_u   + (size_t)b*T_*DI + ch;
    float*       yp   = g_y   + (size_t)b*T_*DI + ch;

    for (int t = 0; t < T_; t += 2){
        // hoist all loads + exps ahead of the serial h chain
        float v0  = dblp[(size_t)t*48 + lane];
        float v1  = dblp[(size_t)(t+1)*48 + lane];
        float dt0 = dtp[(size_t)t*DI];
        float dt1 = dtp[(size_t)(t+1)*DI];
        float u0  = up[(size_t)t*DI];
        float u1  = up[(size_t)(t+1)*DI];
        float dA0 = __expf(dt0 * A);
        float dA1 = __expf(dt1 * A);
        float B0  = __shfl_sync(0xffffffffu, v0, s);
        float C0  = __shfl_sync(0xffffffffu, v0, s + 16);
        float B1  = __shfl_sync(0xffffffffu, v1, s);
        float C1  = __shfl_sync(0xffffffffu, v1, s + 16);

        h = fmaf(h, dA0, (dt0*u0)*B0);
        float p0 = h * C0;
        p0 += __shfl_xor_sync(0xffffffffu, p0, 1);
        p0 += __shfl_xor_sync(0xffffffffu, p0, 2);
        p0 += __shfl_xor_sync(0xffffffffu, p0, 4);
        p0 += __shfl_xor_sync(0xffffffffu, p0, 8);

        h = fmaf(h, dA1, (dt1*u1)*B1);
        float p1 = h * C1;
        p1 += __shfl_xor_sync(0xffffffffu, p1, 1);
        p1 += __shfl_xor_sync(0xffffffffu, p1, 2);
        p1 += __shfl_xor_sync(0xffffffffu, p1, 4);
        p1 += __shfl_xor_sync(0xffffffffu, p1, 8);

        if (s == 0){
            yp[(size_t)t*DI]     = fmaf(u0, Dd, p0);
            yp[(size_t)(t+1)*DI] = fmaf(u1, Dd, p1);
        }
    }
}

// ---------------- masked mean pool over time ----------------
__global__ void k_pool(const int* __restrict__ lengths){
    int b = blockIdx.x, tid = threadIdx.x;   // 256 threads
    int len = lengths[b];
    if (len < 1) len = 1;
    const float* p = g_xln + (size_t)b*T_*DM + tid;
    float s = 0.f;
    for (int t = 0; t < len; t++) s += p[(size_t)t*DM];
    g_pool[b*DM + tid] = s / (float)len;
}

// ---------------- classifier head ----------------
__global__ void k_head(const float* __restrict__ c1w, const float* __restrict__ c1b,
                       const float* __restrict__ c2w, const float* __restrict__ c2b,
                       float* __restrict__ out){
    int b = blockIdx.x, tid = threadIdx.x;   // 128 threads
    __shared__ float ps[DM];
    __shared__ float z1[DM/2];
    ps[tid]       = g_pool[b*DM + tid];
    ps[tid + 128] = g_pool[b*DM + tid + 128];
    __syncthreads();
    float a = c1b[tid];
    #pragma unroll 4
    for (int k = 0; k < DM; k++) a = fmaf(ps[k], c1w[tid*DM + k], a);
    z1[tid] = silu_f(a);
    __syncthreads();
    if (tid < NCLS){
        float o = c2b[tid];
        #pragma unroll 4
        for (int k = 0; k < 128; k++) o = fmaf(z1[k], c2w[tid*128 + k], o);
        out[b*NCLS + tid] = o;
    }
}

// ---------------- host launch ----------------
extern "C" void kernel_launch(void* const* d_in, const int* in_sizes, int n_in,
                              void* d_out, int out_size){
    const float* x      = (const float*)d_in[0];
    const int*   lens   = (const int*)  d_in[1];
    const float* proj_w = (const float*)d_in[2];
    const float* proj_b = (const float*)d_in[3];
    const float* pln_g  = (const float*)d_in[4];
    const float* pln_b  = (const float*)d_in[5];
    const float* ln_g   = (const float*)d_in[6];
    const float* ln_b   = (const float*)d_in[7];
    const float* in_w   = (const float*)d_in[8];
    const float* conv_w = (const float*)d_in[9];
    const float* conv_b = (const float*)d_in[10];
    const float* xp_w   = (const float*)d_in[11];
    const float* dt_w   = (const float*)d_in[12];
    const float* dt_b   = (const float*)d_in[13];
    const float* A_log  = (const float*)d_in[14];
    const float* Dp     = (const float*)d_in[15];
    const float* out_w  = (const float*)d_in[16];
    const float* pre_g  = (const float*)d_in[17];
    const float* pre_b  = (const float*)d_in[18];
    const float* c1_w   = (const float*)d_in[19];
    const float* c1_b   = (const float*)d_in[20];
    const float* c2_w   = (const float*)d_in[21];
    const float* c2_b   = (const float*)d_in[22];
    float* out = (float*)d_out;

    float *p_xln, *p_xz, *p_y, *p_h;
    cudaGetSymbolAddress((void**)&p_xln, g_xln);
    cudaGetSymbolAddress((void**)&p_xz,  g_xz);
    cudaGetSymbolAddress((void**)&p_y,   g_y);
    cudaGetSymbolAddress((void**)&p_h,   g_h);

    k_inproj<<<NTOK, DM>>>(x, proj_w, proj_b, pln_g, pln_b);

    for (int i = 0; i < NL; i++){
        k_ln<<<NTOK, DM>>>(ln_g + i*DM, ln_b + i*DM);

        dim3 gin(2*DI/64, NTOK/128);       // (16, 64)
        sgemm2<0,0><<<gin, 256>>>(p_xln, p_xz, in_w + (size_t)i*2*DI*DM, p_xz,
                                  NTOK, 2*DI, DM);

        k_conv2<<<NTOK*DI/4/256, 256>>>(conv_w + i*DI*4, conv_b + i*DI);

        k_xpdt2<<<NTOK/16, 256>>>(xp_w + (size_t)i*48*DI,
                                  dt_w + (size_t)i*DI*DR,
                                  dt_b + i*DI);

        k_scan<<<512, 256>>>(A_log + (size_t)i*DI*DS, Dp + i*DI);

        dim3 gout(DM/64, NTOK/128);        // (4, 64)
        sgemm2<1,1><<<gout, 256>>>(p_y, p_xz, out_w + (size_t)i*DM*DI, p_h,
                                   NTOK, DM, DI);
    }

    k_ln<<<NTOK, DM>>>(pre_g, pre_b);
    k_pool<<<B_, DM>>>(lens);
    k_head<<<B_, 128>>>(c1_w, c1_b, c2_w, c2_b, out);
}

// round 3
// speedup vs baseline: 2.9225x; 1.1668x over previous
#include <cuda_runtime.h>
#include <cuda_bf16.h>
#include <math.h>

#define B_    16
#define T_    512
#define FEAT_ 40
#define DM    256
#define DI    512
#define DS    16
#define DR    16
#define NL    8
#define NTOK  (B_*T_)
#define NCLS  35

// ---------------- scratch (device globals: allocation-free) ----------------
__device__ __align__(16) float g_h  [NTOK*DM];     // residual stream
__device__ __align__(16) float g_xln[NTOK*DM];     // final layernorm out (pool input)
__device__ __align__(16) float g_xz [NTOK*2*DI];   // in-proj output (u|z)
__device__ __align__(16) float g_u  [NTOK*DI];     // conv+silu output
__device__ __align__(16) float g_dbl[NTOK*48];     // x-proj output (dt_lr|B|C)
__device__ __align__(16) float g_dt [NTOK*DI];     // softplus dt
__device__ __align__(16) float g_y  [NTOK*DI];     // scan output
__device__ __align__(16) float g_pool[B_*DM];

// bf16 split buffers (activations + weights)
__device__ __align__(16) __nv_bfloat16 g_ah[NTOK*DI];
__device__ __align__(16) __nv_bfloat16 g_al[NTOK*DI];
__device__ __align__(16) __nv_bfloat16 g_inwh [NL*2*DI*DM];
__device__ __align__(16) __nv_bfloat16 g_inwl [NL*2*DI*DM];
__device__ __align__(16) __nv_bfloat16 g_outwh[NL*DM*DI];
__device__ __align__(16) __nv_bfloat16 g_outwl[NL*DM*DI];

__device__ __forceinline__ float silu_f(float x){ return x / (1.f + __expf(-x)); }

// ---------------- weight split: fp32 -> bf16 hi/lo ----------------
__global__ void k_wsplit(const float* __restrict__ in_w, const float* __restrict__ out_w){
    const int n1 = NL*2*DI*DM;
    const int n2 = NL*DM*DI;
    for (int i = blockIdx.x*blockDim.x + threadIdx.x; i < n1 + n2; i += gridDim.x*blockDim.x){
        float v; __nv_bfloat16 *ph, *pl;
        if (i < n1){ v = in_w[i];  ph = g_inwh  + i;      pl = g_inwl  + i; }
        else       { v = out_w[i-n1]; ph = g_outwh + (i-n1); pl = g_outwl + (i-n1); }
        __nv_bfloat16 h = __float2bfloat16(v);
        *ph = h;
        *pl = __float2bfloat16(v - __bfloat162float(h));
    }
}

// ---------------- input projection + LN + silu ----------------
__global__ void k_inproj(const float* __restrict__ x, const float* __restrict__ pw,
                         const float* __restrict__ pb, const float* __restrict__ g,
                         const float* __restrict__ bb){
    int tok = blockIdx.x, tid = threadIdx.x;
    __shared__ float xs[FEAT_];
    __shared__ float ws[8], wq[8];
    if (tid < FEAT_) xs[tid] = x[tok*FEAT_ + tid];
    __syncthreads();
    float acc = pb[tid];
    #pragma unroll
    for (int f = 0; f < FEAT_; f++) acc += xs[f] * pw[tid*FEAT_ + f];
    float s = acc, q = acc*acc;
    #pragma unroll
    for (int o = 16; o; o >>= 1){ s += __shfl_xor_sync(~0u, s, o); q += __shfl_xor_sync(~0u, q, o); }
    int w = tid >> 5, l = tid & 31;
    if (l == 0){ ws[w] = s; wq[w] = q; }
    __syncthreads();
    if (tid < 32){
        float a = (l < 8) ? ws[l] : 0.f, b = (l < 8) ? wq[l] : 0.f;
        #pragma unroll
        for (int o = 4; o; o >>= 1){ a += __shfl_xor_sync(~0u, a, o); b += __shfl_xor_sync(~0u, b, o); }
        if (l == 0){ ws[0] = a; wq[0] = b; }
    }
    __syncthreads();
    float m   = ws[0] * (1.f/DM);
    float var = wq[0] * (1.f/DM) - m*m;
    float r   = rsqrtf(var + 1e-5f);
    float v   = (acc - m) * r * g[tid] + bb[tid];
    g_h[tok*DM + tid] = silu_f(v);
}

// ---------------- layernorm of g_h; SPLIT: emit bf16 hi/lo (K=256 packed) --
template<int SPLIT>
__global__ void k_ln2(const float* __restrict__ g, const float* __restrict__ bb){
    int tok = blockIdx.x, tid = threadIdx.x;
    __shared__ float ws[8], wq[8];
    float v = g_h[tok*DM + tid];
    float s = v, q = v*v;
    #pragma unroll
    for (int o = 16; o; o >>= 1){ s += __shfl_xor_sync(~0u, s, o); q += __shfl_xor_sync(~0u, q, o); }
    int w = tid >> 5, l = tid & 31;
    if (l == 0){ ws[w] = s; wq[w] = q; }
    __syncthreads();
    if (tid < 32){
        float a = (l < 8) ? ws[l] : 0.f, b = (l < 8) ? wq[l] : 0.f;
        #pragma unroll
        for (int o = 4; o; o >>= 1){ a += __shfl_xor_sync(~0u, a, o); b += __shfl_xor_sync(~0u, b, o); }
        if (l == 0){ ws[0] = a; wq[0] = b; }
    }
    __syncthreads();
    float m   = ws[0] * (1.f/DM);
    float var = wq[0] * (1.f/DM) - m*m;
    float r   = rsqrtf(var + 1e-5f);
    float o   = (v - m) * r * g[tid] + bb[tid];
    if (SPLIT){
        __nv_bfloat16 h = __float2bfloat16(o);
        g_ah[(size_t)tok*DM + tid] = h;
        g_al[(size_t)tok*DM + tid] = __float2bfloat16(o - __bfloat162float(h));
    } else {
        g_xln[(size_t)tok*DM + tid] = o;
    }
}

// ---------------- gate + split: A = y*silu(z) -> bf16 hi/lo (K=512 packed) -
__global__ void k_gate_split(){
    int idx = blockIdx.x * blockDim.x + threadIdx.x;   // < NTOK*DI
    int d   = idx & (DI-1);
    int tok = idx >> 9;
    float z = g_xz[(size_t)tok*2*DI + DI + d];
    float a = g_y[idx] * silu_f(z);
    __nv_bfloat16 h = __float2bfloat16(a);
    g_ah[idx] = h;
    g_al[idx] = __float2bfloat16(a - __bfloat162float(h));
}

// ---------------- bf16 tensor-core GEMM with 2-way split (3 MMA passes) ----
// C[M,N] (+)= (Ah+Al)[M,K] @ (Wh+Wl)[N,K]^T   (drops Al*Wl term, err ~2^-18)
// BM=128, BN=64, BK=32, 256 threads (8 warps, 4Mx2N), warp tile 32x32.
__device__ __forceinline__ void mma16816(float c[4], const unsigned a[4], const unsigned b[2]){
    asm volatile(
        "mma.sync.aligned.m16n8k16.row.col.f32.bf16.bf16.f32 "
        "{%0,%1,%2,%3}, {%4,%5,%6,%7}, {%8,%9}, {%0,%1,%2,%3};"
        : "+f"(c[0]), "+f"(c[1]), "+f"(c[2]), "+f"(c[3])
        : "r"(a[0]), "r"(a[1]), "r"(a[2]), "r"(a[3]), "r"(b[0]), "r"(b[1]));
}

template<int ACC>
__global__ void __launch_bounds__(256)
mgemm(const __nv_bfloat16* __restrict__ Ah, const __nv_bfloat16* __restrict__ Al,
      const __nv_bfloat16* __restrict__ Wh, const __nv_bfloat16* __restrict__ Wl,
      float* __restrict__ C, int M, int N, int K){
    __shared__ __align__(16) __nv_bfloat16 sAh[128][40];
    __shared__ __align__(16) __nv_bfloat16 sAl[128][40];
    __shared__ __align__(16) __nv_bfloat16 sWh[64][40];
    __shared__ __align__(16) __nv_bfloat16 sWl[64][40];
    const int tid  = threadIdx.x, lane = tid & 31, w = tid >> 5;
    const int wm   = (w & 3) * 32, wn = (w >> 2) * 32;
    const int g    = lane >> 2, t = lane & 3;
    const int bm   = blockIdx.y * 128, bn = blockIdx.x * 64;
    const int ar   = tid >> 2, ac = tid & 3;

    float acc[2][4][4] = {};

    for (int k0 = 0; k0 < K; k0 += 32){
        // stage tiles (each thread: 6 x uint4)
        *(uint4*)&sAh[ar][ac*8]    = *(const uint4*)(Ah + (size_t)(bm+ar)   *K + k0 + ac*8);
        *(uint4*)&sAh[ar+64][ac*8] = *(const uint4*)(Ah + (size_t)(bm+ar+64)*K + k0 + ac*8);
        *(uint4*)&sAl[ar][ac*8]    = *(const uint4*)(Al + (size_t)(bm+ar)   *K + k0 + ac*8);
        *(uint4*)&sAl[ar+64][ac*8] = *(const uint4*)(Al + (size_t)(bm+ar+64)*K + k0 + ac*8);
        *(uint4*)&sWh[ar][ac*8]    = *(const uint4*)(Wh + (size_t)(bn+ar)   *K + k0 + ac*8);
        *(uint4*)&sWl[ar][ac*8]    = *(const uint4*)(Wl + (size_t)(bn+ar)   *K + k0 + ac*8);
        __syncthreads();

        #pragma unroll
        for (int kk = 0; kk < 32; kk += 16){
            unsigned fah[2][4], fal[2][4], fwh[4][2], fwl[4][2];
            #pragma unroll
            for (int i = 0; i < 2; i++){
                int r = wm + i*16 + g;
                fah[i][0] = *(const unsigned*)&sAh[r  ][kk + 2*t];
                fah[i][1] = *(const unsigned*)&sAh[r+8][kk + 2*t];
                fah[i][2] = *(const unsigned*)&sAh[r  ][kk + 2*t + 8];
                fah[i][3] = *(const unsigned*)&sAh[r+8][kk + 2*t + 8];
                fal[i][0] = *(const unsigned*)&sAl[r  ][kk + 2*t];
                fal[i][1] = *(const unsigned*)&sAl[r+8][kk + 2*t];
                fal[i][2] = *(const unsigned*)&sAl[r  ][kk + 2*t + 8];
                fal[i][3] = *(const unsigned*)&sAl[r+8][kk + 2*t + 8];
            }
            #pragma unroll
            for (int j = 0; j < 4; j++){
                int n = wn + j*8 + g;
                fwh[j][0] = *(const unsigned*)&sWh[n][kk + 2*t];
                fwh[j][1] = *(const unsigned*)&sWh[n][kk + 2*t + 8];
                fwl[j][0] = *(const unsigned*)&sWl[n][kk + 2*t];
                fwl[j][1] = *(const unsigned*)&sWl[n][kk + 2*t + 8];
            }
            #pragma unroll
            for (int i = 0; i < 2; i++)
                #pragma unroll
                for (int j = 0; j < 4; j++){
                    mma16816(acc[i][j], fah[i], fwh[j]);
                    mma16816(acc[i][j], fah[i], fwl[j]);
                    mma16816(acc[i][j], fal[i], fwh[j]);
                }
        }
        __syncthreads();
    }

    #pragma unroll
    for (int i = 0; i < 2; i++){
        #pragma unroll
        for (int j = 0; j < 4; j++){
            int row = bm + wm + i*16 + g;
            int col = bn + wn + j*8 + 2*t;
            float2* p0 = (float2*)&C[(size_t)row    *N + col];
            float2* p1 = (float2*)&C[(size_t)(row+8)*N + col];
            float2 v0, v1;
            if (ACC){
                v0 = *p0; v1 = *p1;
                v0.x += acc[i][j][0]; v0.y += acc[i][j][1];
                v1.x += acc[i][j][2]; v1.y += acc[i][j][3];
            } else {
                v0.x = acc[i][j][0]; v0.y = acc[i][j][1];
                v1.x = acc[i][j][2]; v1.y = acc[i][j][3];
            }
            *p0 = v0; *p1 = v1;
        }
    }
}

// ---------------- causal depthwise conv (k=4) + silu, 4 t per thread -------
__global__ void k_conv2(const float* __restrict__ cw, const float* __restrict__ cb){
    int idx = blockIdx.x * blockDim.x + threadIdx.x;  // < NTOK*DI/4
    int d  = idx & (DI-1);
    int q  = (idx >> 9) & (T_/4 - 1);
    int b  = idx >> 16;
    int t0 = q * 4;
    const float* base = g_xz + (size_t)b * T_ * 2*DI + d;
    float w0 = cw[d*4+0], w1 = cw[d*4+1], w2 = cw[d*4+2], w3 = cw[d*4+3];
    float bias = cb[d];
    float xv[7];
    #pragma unroll
    for (int j = 0; j < 7; j++){
        int tt = t0 - 3 + j;
        xv[j] = (tt >= 0) ? base[(size_t)tt * 2*DI] : 0.f;
    }
    float* op = g_u + ((size_t)b * T_ + t0) * DI + d;
    #pragma unroll
    for (int i = 0; i < 4; i++){
        float a = bias + w0*xv[i] + w1*xv[i+1] + w2*xv[i+2] + w3*xv[i+3];
        op[(size_t)i * DI] = silu_f(a);
    }
}

// ---------------- x-proj + dt-proj + softplus, 16 tokens per block ---------
__global__ void __launch_bounds__(256)
k_xpdt2(const float* __restrict__ xpw, const float* __restrict__ dtw,
        const float* __restrict__ dtb){
    __shared__ float us[16][516];
    __shared__ float dbls[16][48];
    const int tid  = threadIdx.x;
    const int tok0 = blockIdx.x * 16;

    #pragma unroll
    for (int i = 0; i < 8; i++){
        int idx = i*256 + tid;
        int tok = idx >> 7;
        int k   = (idx & 127) * 4;
        float4 v = *(const float4*)(g_u + (size_t)(tok0 + tok)*DI + k);
        *(float4*)&us[tok][k] = v;
    }
    __syncthreads();

    #pragma unroll
    for (int r = 0; r < 3; r++){
        int idx = r*256 + tid;
        int j   = idx % 48;
        int tok = idx / 48;
        const float* wp = xpw + (size_t)j * DI;
        float a = 0.f;
        #pragma unroll 8
        for (int k = 0; k < DI; k += 4){
            float4 w = *(const float4*)(wp + k);
            float4 u = *(const float4*)&us[tok][k];
            a = fmaf(u.x, w.x, a); a = fmaf(u.y, w.y, a);
            a = fmaf(u.z, w.z, a); a = fmaf(u.w, w.w, a);
        }
        dbls[tok][j] = a;
        g_dbl[(size_t)(tok0 + tok)*48 + j] = a;
    }
    __syncthreads();

    #pragma unroll 2
    for (int rep = 0; rep < 32; rep++){
        int idx = rep*256 + tid;
        int d   = idx & (DI-1);
        int tok = idx >> 9;
        const float* wp = dtw + (size_t)d * DR;
        float a = dtb[d];
        #pragma unroll
        for (int rr = 0; rr < 16; rr += 4){
            float4 w = *(const float4*)(wp + rr);
            float4 x = *(const float4*)&dbls[tok][rr];
            a = fmaf(x.x, w.x, a); a = fmaf(x.y, w.y, a);
            a = fmaf(x.z, w.z, a); a = fmaf(x.w, w.w, a);
        }
        float sp = (a > 20.f) ? a : log1pf(__expf(a));
        g_dt[(size_t)(tok0 + tok)*DI + d] = sp;
    }
}

// ---------------- selective scan: warp = 2 channels x 16 states ------------
__global__ void k_scan(const float* __restrict__ Alog, const float* __restrict__ Dp){
    int w    = blockIdx.x * 8 + (threadIdx.x >> 5);
    int lane = threadIdx.x & 31;
    int b    = w >> 8;
    int pair = w & 255;
    int ch   = pair*2 + (lane >> 4);
    int s    = lane & 15;
    float A  = -__expf(Alog[ch*DS + s]);
    float Dd = Dp[ch];
    float h  = 0.f;
    const float* dblp = g_dbl + (size_t)b*T_*48 + 16;
    const float* dtp  = g_dt  + (size_t)b*T_*DI + ch;
    const float* up   = g_u   + (size_t)b*T_*DI + ch;
    float*       yp   = g_y   + (size_t)b*T_*DI + ch;

    for (int t = 0; t < T_; t += 2){
        float v0  = dblp[(size_t)t*48 + lane];
        float v1  = dblp[(size_t)(t+1)*48 + lane];
        float dt0 = dtp[(size_t)t*DI];
        float dt1 = dtp[(size_t)(t+1)*DI];
        float u0  = up[(size_t)t*DI];
        float u1  = up[(size_t)(t+1)*DI];
        float dA0 = __expf(dt0 * A);
        float dA1 = __expf(dt1 * A);
        float B0  = __shfl_sync(0xffffffffu, v0, s);
        float C0  = __shfl_sync(0xffffffffu, v0, s + 16);
        float B1  = __shfl_sync(0xffffffffu, v1, s);
        float C1  = __shfl_sync(0xffffffffu, v1, s + 16);

        h = fmaf(h, dA0, (dt0*u0)*B0);
        float p0 = h * C0;
        p0 += __shfl_xor_sync(0xffffffffu, p0, 1);
        p0 += __shfl_xor_sync(0xffffffffu, p0, 2);
        p0 += __shfl_xor_sync(0xffffffffu, p0, 4);
        p0 += __shfl_xor_sync(0xffffffffu, p0, 8);

        h = fmaf(h, dA1, (dt1*u1)*B1);
        float p1 = h * C1;
        p1 += __shfl_xor_sync(0xffffffffu, p1, 1);
        p1 += __shfl_xor_sync(0xffffffffu, p1, 2);
        p1 += __shfl_xor_sync(0xffffffffu, p1, 4);
        p1 += __shfl_xor_sync(0xffffffffu, p1, 8);

        if (s == 0){
            yp[(size_t)t*DI]     = fmaf(u0, Dd, p0);
            yp[(size_t)(t+1)*DI] = fmaf(u1, Dd, p1);
        }
    }
}

// ---------------- masked mean pool over time ----------------
__global__ void k_pool(const int* __restrict__ lengths){
    int b = blockIdx.x, tid = threadIdx.x;
    int len = lengths[b];
    if (len < 1) len = 1;
    const float* p = g_xln + (size_t)b*T_*DM + tid;
    float s = 0.f;
    for (int t = 0; t < len; t++) s += p[(size_t)t*DM];
    g_pool[b*DM + tid] = s / (float)len;
}

// ---------------- classifier head ----------------
__global__ void k_head(const float* __restrict__ c1w, const float* __restrict__ c1b,
                       const float* __restrict__ c2w, const float* __restrict__ c2b,
                       float* __restrict__ out){
    int b = blockIdx.x, tid = threadIdx.x;
    __shared__ float ps[DM];
    __shared__ float z1[DM/2];
    ps[tid]       = g_pool[b*DM + tid];
    ps[tid + 128] = g_pool[b*DM + tid + 128];
    __syncthreads();
    float a = c1b[tid];
    #pragma unroll 4
    for (int k = 0; k < DM; k++) a = fmaf(ps[k], c1w[tid*DM + k], a);
    z1[tid] = silu_f(a);
    __syncthreads();
    if (tid < NCLS){
        float o = c2b[tid];
        #pragma unroll 4
        for (int k = 0; k < 128; k++) o = fmaf(z1[k], c2w[tid*128 + k], o);
        out[b*NCLS + tid] = o;
    }
}

// ---------------- host launch ----------------
extern "C" void kernel_launch(void* const* d_in, const int* in_sizes, int n_in,
                              void* d_out, int out_size){
    const float* x      = (const float*)d_in[0];
    const int*   lens   = (const int*)  d_in[1];
    const float* proj_w = (const float*)d_in[2];
    const float* proj_b = (const float*)d_in[3];
    const float* pln_g  = (const float*)d_in[4];
    const float* pln_b  = (const float*)d_in[5];
    const float* ln_g   = (const float*)d_in[6];
    const float* ln_b   = (const float*)d_in[7];
    const float* in_w   = (const float*)d_in[8];
    const float* conv_w = (const float*)d_in[9];
    const float* conv_b = (const float*)d_in[10];
    const float* xp_w   = (const float*)d_in[11];
    const float* dt_w   = (const float*)d_in[12];
    const float* dt_b   = (const float*)d_in[13];
    const float* A_log  = (const float*)d_in[14];
    const float* Dp     = (const float*)d_in[15];
    const float* out_w  = (const float*)d_in[16];
    const float* pre_g  = (const float*)d_in[17];
    const float* pre_b  = (const float*)d_in[18];
    const float* c1_w   = (const float*)d_in[19];
    const float* c1_b   = (const float*)d_in[20];
    const float* c2_w   = (const float*)d_in[21];
    const float* c2_b   = (const float*)d_in[22];
    float* out = (float*)d_out;

    float *p_xz, *p_h;
    __nv_bfloat16 *p_ah, *p_al, *p_inwh, *p_inwl, *p_outwh, *p_outwl;
    cudaGetSymbolAddress((void**)&p_xz,    g_xz);
    cudaGetSymbolAddress((void**)&p_h,     g_h);
    cudaGetSymbolAddress((void**)&p_ah,    g_ah);
    cudaGetSymbolAddress((void**)&p_al,    g_al);
    cudaGetSymbolAddress((void**)&p_inwh,  g_inwh);
    cudaGetSymbolAddress((void**)&p_inwl,  g_inwl);
    cudaGetSymbolAddress((void**)&p_outwh, g_outwh);
    cudaGetSymbolAddress((void**)&p_outwl, g_outwl);

    k_wsplit<<<2048, 256>>>(in_w, out_w);
    k_inproj<<<NTOK, DM>>>(x, proj_w, proj_b, pln_g, pln_b);

    for (int i = 0; i < NL; i++){
        k_ln2<1><<<NTOK, DM>>>(ln_g + i*DM, ln_b + i*DM);

        dim3 gin(2*DI/64, NTOK/128);       // (16, 64)
        mgemm<0><<<gin, 256>>>(p_ah, p_al,
                               p_inwh + (size_t)i*2*DI*DM, p_inwl + (size_t)i*2*DI*DM,
                               p_xz, NTOK, 2*DI, DM);

        k_conv2<<<NTOK*DI/4/256, 256>>>(conv_w + i*DI*4, conv_b + i*DI);

        k_xpdt2<<<NTOK/16, 256>>>(xp_w + (size_t)i*48*DI,
                                  dt_w + (size_t)i*DI*DR,
                                  dt_b + i*DI);

        k_scan<<<512, 256>>>(A_log + (size_t)i*DI*DS, Dp + i*DI);

        k_gate_split<<<NTOK*DI/256, 256>>>();

        dim3 gout(DM/64, NTOK/128);        // (4, 64)
        mgemm<1><<<gout, 256>>>(p_ah, p_al,
                                p_outwh + (size_t)i*DM*DI, p_outwl + (size_t)i*DM*DI,
                                p_h, NTOK, DM, DI);
    }

    k_ln2<0><<<NTOK, DM>>>(pre_g, pre_b);
    k_pool<<<B_, DM>>>(lens);
    k_head<<<B_, 128>>>(c1_w, c1_b, c2_w, c2_b, out);
}

// round 4
// speedup vs baseline: 2.9449x; 1.0077x over previous
#include <cuda_runtime.h>
#include <cuda_bf16.h>
#include <math.h>

#define B_    16
#define T_    512
#define FEAT_ 40
#define DM    256
#define DI    512
#define DS    16
#define DR    16
#define NL    8
#define NTOK  (B_*T_)
#define NCLS  35

// ---------------- scratch (device globals: allocation-free) ----------------
__device__ __align__(16) float g_h  [NTOK*DM];     // residual stream
__device__ __align__(16) float g_xln[NTOK*DM];     // final layernorm out (pool input)
__device__ __align__(16) float g_xz [NTOK*2*DI];   // in-proj output (u|z)
__device__ __align__(16) float g_u  [NTOK*DI];     // conv+silu output
__device__ __align__(16) float g_dbl[NTOK*48];     // x-proj output (dt_lr|B|C)
__device__ __align__(16) float g_dt [NTOK*DI];     // softplus dt
__device__ __align__(16) float g_y  [NTOK*DI];     // scan output
__device__ __align__(16) float g_pool[B_*DM];

// bf16 split buffers (activations + weights)
__device__ __align__(16) __nv_bfloat16 g_ah[NTOK*DI];
__device__ __align__(16) __nv_bfloat16 g_al[NTOK*DI];
__device__ __align__(16) __nv_bfloat16 g_inwh [NL*2*DI*DM];
__device__ __align__(16) __nv_bfloat16 g_inwl [NL*2*DI*DM];
__device__ __align__(16) __nv_bfloat16 g_outwh[NL*DM*DI];
__device__ __align__(16) __nv_bfloat16 g_outwl[NL*DM*DI];

__device__ __forceinline__ float silu_f(float x){ return x / (1.f + __expf(-x)); }

// ---------------- weight split: fp32 -> bf16 hi/lo ----------------
__global__ void k_wsplit(const float* __restrict__ in_w, const float* __restrict__ out_w){
    const int n1 = NL*2*DI*DM;
    const int n2 = NL*DM*DI;
    for (int i = blockIdx.x*blockDim.x + threadIdx.x; i < n1 + n2; i += gridDim.x*blockDim.x){
        float v; __nv_bfloat16 *ph, *pl;
        if (i < n1){ v = in_w[i];  ph = g_inwh  + i;      pl = g_inwl  + i; }
        else       { v = out_w[i-n1]; ph = g_outwh + (i-n1); pl = g_outwl + (i-n1); }
        __nv_bfloat16 h = __float2bfloat16(v);
        *ph = h;
        *pl = __float2bfloat16(v - __bfloat162float(h));
    }
}

// ---------------- input projection + LN + silu ----------------
__global__ void k_inproj(const float* __restrict__ x, const float* __restrict__ pw,
                         const float* __restrict__ pb, const float* __restrict__ g,
                         const float* __restrict__ bb){
    int tok = blockIdx.x, tid = threadIdx.x;
    __shared__ float xs[FEAT_];
    __shared__ float ws[8], wq[8];
    if (tid < FEAT_) xs[tid] = x[tok*FEAT_ + tid];
    __syncthreads();
    float acc = pb[tid];
    #pragma unroll
    for (int f = 0; f < FEAT_; f++) acc += xs[f] * pw[tid*FEAT_ + f];
    float s = acc, q = acc*acc;
    #pragma unroll
    for (int o = 16; o; o >>= 1){ s += __shfl_xor_sync(~0u, s, o); q += __shfl_xor_sync(~0u, q, o); }
    int w = tid >> 5, l = tid & 31;
    if (l == 0){ ws[w] = s; wq[w] = q; }
    __syncthreads();
    if (tid < 32){
        float a = (l < 8) ? ws[l] : 0.f, b = (l < 8) ? wq[l] : 0.f;
        #pragma unroll
        for (int o = 4; o; o >>= 1){ a += __shfl_xor_sync(~0u, a, o); b += __shfl_xor_sync(~0u, b, o); }
        if (l == 0){ ws[0] = a; wq[0] = b; }
    }
    __syncthreads();
    float m   = ws[0] * (1.f/DM);
    float var = wq[0] * (1.f/DM) - m*m;
    float r   = rsqrtf(var + 1e-5f);
    float v   = (acc - m) * r * g[tid] + bb[tid];
    g_h[tok*DM + tid] = silu_f(v);
}

// ---------------- layernorm of g_h; SPLIT: emit bf16 hi/lo ----------------
template<int SPLIT>
__global__ void k_ln2(const float* __restrict__ g, const float* __restrict__ bb){
    int tok = blockIdx.x, tid = threadIdx.x;
    __shared__ float ws[8], wq[8];
    float v = g_h[tok*DM + tid];
    float s = v, q = v*v;
    #pragma unroll
    for (int o = 16; o; o >>= 1){ s += __shfl_xor_sync(~0u, s, o); q += __shfl_xor_sync(~0u, q, o); }
    int w = tid >> 5, l = tid & 31;
    if (l == 0){ ws[w] = s; wq[w] = q; }
    __syncthreads();
    if (tid < 32){
        float a = (l < 8) ? ws[l] : 0.f, b = (l < 8) ? wq[l] : 0.f;
        #pragma unroll
        for (int o = 4; o; o >>= 1){ a += __shfl_xor_sync(~0u, a, o); b += __shfl_xor_sync(~0u, b, o); }
        if (l == 0){ ws[0] = a; wq[0] = b; }
    }
    __syncthreads();
    float m   = ws[0] * (1.f/DM);
    float var = wq[0] * (1.f/DM) - m*m;
    float r   = rsqrtf(var + 1e-5f);
    float o   = (v - m) * r * g[tid] + bb[tid];
    if (SPLIT){
        __nv_bfloat16 h = __float2bfloat16(o);
        g_ah[(size_t)tok*DM + tid] = h;
        g_al[(size_t)tok*DM + tid] = __float2bfloat16(o - __bfloat162float(h));
    } else {
        g_xln[(size_t)tok*DM + tid] = o;
    }
}

// ---------------- gate + split: A = y*silu(z) -> bf16 hi/lo ----------------
__global__ void k_gate_split(){
    int idx = blockIdx.x * blockDim.x + threadIdx.x;   // < NTOK*DI
    int d   = idx & (DI-1);
    int tok = idx >> 9;
    float z = g_xz[(size_t)tok*2*DI + DI + d];
    float a = g_y[idx] * silu_f(z);
    __nv_bfloat16 h = __float2bfloat16(a);
    g_ah[idx] = h;
    g_al[idx] = __float2bfloat16(a - __bfloat162float(h));
}

// ---------------- bf16 tensor-core GEMM with 2-way split (3 MMA passes) ----
__device__ __forceinline__ void mma16816(float c[4], const unsigned a[4], const unsigned b[2]){
    asm volatile(
        "mma.sync.aligned.m16n8k16.row.col.f32.bf16.bf16.f32 "
        "{%0,%1,%2,%3}, {%4,%5,%6,%7}, {%8,%9}, {%0,%1,%2,%3};"
        : "+f"(c[0]), "+f"(c[1]), "+f"(c[2]), "+f"(c[3])
        : "r"(a[0]), "r"(a[1]), "r"(a[2]), "r"(a[3]), "r"(b[0]), "r"(b[1]));
}

template<int ACC>
__global__ void __launch_bounds__(256)
mgemm(const __nv_bfloat16* __restrict__ Ah, const __nv_bfloat16* __restrict__ Al,
      const __nv_bfloat16* __restrict__ Wh, const __nv_bfloat16* __restrict__ Wl,
      float* __restrict__ C, int M, int N, int K){
    __shared__ __align__(16) __nv_bfloat16 sAh[128][40];
    __shared__ __align__(16) __nv_bfloat16 sAl[128][40];
    __shared__ __align__(16) __nv_bfloat16 sWh[64][40];
    __shared__ __align__(16) __nv_bfloat16 sWl[64][40];
    const int tid  = threadIdx.x, lane = tid & 31, w = tid >> 5;
    const int wm   = (w & 3) * 32, wn = (w >> 2) * 32;
    const int g    = lane >> 2, t = lane & 3;
    const int bm   = blockIdx.y * 128, bn = blockIdx.x * 64;
    const int ar   = tid >> 2, ac = tid & 3;

    float acc[2][4][4] = {};

    for (int k0 = 0; k0 < K; k0 += 32){
        *(uint4*)&sAh[ar][ac*8]    = *(const uint4*)(Ah + (size_t)(bm+ar)   *K + k0 + ac*8);
        *(uint4*)&sAh[ar+64][ac*8] = *(const uint4*)(Ah + (size_t)(bm+ar+64)*K + k0 + ac*8);
        *(uint4*)&sAl[ar][ac*8]    = *(const uint4*)(Al + (size_t)(bm+ar)   *K + k0 + ac*8);
        *(uint4*)&sAl[ar+64][ac*8] = *(const uint4*)(Al + (size_t)(bm+ar+64)*K + k0 + ac*8);
        *(uint4*)&sWh[ar][ac*8]    = *(const uint4*)(Wh + (size_t)(bn+ar)   *K + k0 + ac*8);
        *(uint4*)&sWl[ar][ac*8]    = *(const uint4*)(Wl + (size_t)(bn+ar)   *K + k0 + ac*8);
        __syncthreads();

        #pragma unroll
        for (int kk = 0; kk < 32; kk += 16){
            unsigned fah[2][4], fal[2][4], fwh[4][2], fwl[4][2];
            #pragma unroll
            for (int i = 0; i < 2; i++){
                int r = wm + i*16 + g;
                fah[i][0] = *(const unsigned*)&sAh[r  ][kk + 2*t];
                fah[i][1] = *(const unsigned*)&sAh[r+8][kk + 2*t];
                fah[i][2] = *(const unsigned*)&sAh[r  ][kk + 2*t + 8];
                fah[i][3] = *(const unsigned*)&sAh[r+8][kk + 2*t + 8];
                fal[i][0] = *(const unsigned*)&sAl[r  ][kk + 2*t];
                fal[i][1] = *(const unsigned*)&sAl[r+8][kk + 2*t];
                fal[i][2] = *(const unsigned*)&sAl[r  ][kk + 2*t + 8];
                fal[i][3] = *(const unsigned*)&sAl[r+8][kk + 2*t + 8];
            }
            #pragma unroll
            for (int j = 0; j < 4; j++){
                int n = wn + j*8 + g;
                fwh[j][0] = *(const unsigned*)&sWh[n][kk + 2*t];
                fwh[j][1] = *(const unsigned*)&sWh[n][kk + 2*t + 8];
                fwl[j][0] = *(const unsigned*)&sWl[n][kk + 2*t];
                fwl[j][1] = *(const unsigned*)&sWl[n][kk + 2*t + 8];
            }
            #pragma unroll
            for (int i = 0; i < 2; i++)
                #pragma unroll
                for (int j = 0; j < 4; j++){
                    mma16816(acc[i][j], fah[i], fwh[j]);
                    mma16816(acc[i][j], fah[i], fwl[j]);
                    mma16816(acc[i][j], fal[i], fwh[j]);
                }
        }
        __syncthreads();
    }

    #pragma unroll
    for (int i = 0; i < 2; i++){
        #pragma unroll
        for (int j = 0; j < 4; j++){
            int row = bm + wm + i*16 + g;
            int col = bn + wn + j*8 + 2*t;
            float2* p0 = (float2*)&C[(size_t)row    *N + col];
            float2* p1 = (float2*)&C[(size_t)(row+8)*N + col];
            float2 v0, v1;
            if (ACC){
                v0 = *p0; v1 = *p1;
                v0.x += acc[i][j][0]; v0.y += acc[i][j][1];
                v1.x += acc[i][j][2]; v1.y += acc[i][j][3];
            } else {
                v0.x = acc[i][j][0]; v0.y = acc[i][j][1];
                v1.x = acc[i][j][2]; v1.y = acc[i][j][3];
            }
            *p0 = v0; *p1 = v1;
        }
    }
}

// ---------------- causal depthwise conv (k=4) + silu, 4 t per thread -------
__global__ void k_conv2(const float* __restrict__ cw, const float* __restrict__ cb){
    int idx = blockIdx.x * blockDim.x + threadIdx.x;  // < NTOK*DI/4
    int d  = idx & (DI-1);
    int q  = (idx >> 9) & (T_/4 - 1);
    int b  = idx >> 16;
    int t0 = q * 4;
    const float* base = g_xz + (size_t)b * T_ * 2*DI + d;
    float w0 = cw[d*4+0], w1 = cw[d*4+1], w2 = cw[d*4+2], w3 = cw[d*4+3];
    float bias = cb[d];
    float xv[7];
    #pragma unroll
    for (int j = 0; j < 7; j++){
        int tt = t0 - 3 + j;
        xv[j] = (tt >= 0) ? base[(size_t)tt * 2*DI] : 0.f;
    }
    float* op = g_u + ((size_t)b * T_ + t0) * DI + d;
    #pragma unroll
    for (int i = 0; i < 4; i++){
        float a = bias + w0*xv[i] + w1*xv[i+1] + w2*xv[i+2] + w3*xv[i+3];
        op[(size_t)i * DI] = silu_f(a);
    }
}

// ---------------- x-proj + dt-proj + softplus, 16 tokens per block ---------
__global__ void __launch_bounds__(256)
k_xpdt2(const float* __restrict__ xpw, const float* __restrict__ dtw,
        const float* __restrict__ dtb){
    __shared__ float us[16][516];
    __shared__ float dbls[16][48];
    const int tid  = threadIdx.x;
    const int tok0 = blockIdx.x * 16;

    #pragma unroll
    for (int i = 0; i < 8; i++){
        int idx = i*256 + tid;
        int tok = idx >> 7;
        int k   = (idx & 127) * 4;
        float4 v = *(const float4*)(g_u + (size_t)(tok0 + tok)*DI + k);
        *(float4*)&us[tok][k] = v;
    }
    __syncthreads();

    #pragma unroll
    for (int r = 0; r < 3; r++){
        int idx = r*256 + tid;
        int j   = idx % 48;
        int tok = idx / 48;
        const float* wp = xpw + (size_t)j * DI;
        float a = 0.f;
        #pragma unroll 8
        for (int k = 0; k < DI; k += 4){
            float4 w = *(const float4*)(wp + k);
            float4 u = *(const float4*)&us[tok][k];
            a = fmaf(u.x, w.x, a); a = fmaf(u.y, w.y, a);
            a = fmaf(u.z, w.z, a); a = fmaf(u.w, w.w, a);
        }
        dbls[tok][j] = a;
        g_dbl[(size_t)(tok0 + tok)*48 + j] = a;
    }
    __syncthreads();

    #pragma unroll 2
    for (int rep = 0; rep < 32; rep++){
        int idx = rep*256 + tid;
        int d   = idx & (DI-1);
        int tok = idx >> 9;
        const float* wp = dtw + (size_t)d * DR;
        float a = dtb[d];
        #pragma unroll
        for (int rr = 0; rr < 16; rr += 4){
            float4 w = *(const float4*)(wp + rr);
            float4 x = *(const float4*)&dbls[tok][rr];
            a = fmaf(x.x, w.x, a); a = fmaf(x.y, w.y, a);
            a = fmaf(x.z, w.z, a); a = fmaf(x.w, w.w, a);
        }
        float sp = (a > 20.f) ? a : log1pf(__expf(a));
        g_dt[(size_t)(tok0 + tok)*DI + d] = sp;
    }
}

// ---------------- selective scan v3: software-pipelined, unroll 8 ----------
// warp = 2 channels x 16 states; chunk of 8 timesteps staged in registers,
// loads for chunk k+1 issued before compute of chunk k.
__global__ void __launch_bounds__(256)
k_scan(const float* __restrict__ Alog, const float* __restrict__ Dp){
    int w    = blockIdx.x * 8 + (threadIdx.x >> 5);
    int lane = threadIdx.x & 31;
    int b    = w >> 8;
    int pair = w & 255;
    int ch   = pair*2 + (lane >> 4);
    int s    = lane & 15;
    float A  = -__expf(Alog[ch*DS + s]);
    float Dd = Dp[ch];
    float h  = 0.f;
    const float* dblp = g_dbl + (size_t)b*T_*48 + 16;
    const float* dtp  = g_dt  + (size_t)b*T_*DI + ch;
    const float* up   = g_u   + (size_t)b*T_*DI + ch;
    float*       yp   = g_y   + (size_t)b*T_*DI + ch;

    float v[8], dtv[8], uv[8];
    #pragma unroll
    for (int j = 0; j < 8; j++){
        v[j]   = dblp[j*48 + lane];
        dtv[j] = dtp[(size_t)j*DI];
        uv[j]  = up[(size_t)j*DI];
    }

    for (int t0 = 0; t0 < T_; t0 += 8){
        float nv[8], ndt[8], nu[8];
        if (t0 + 8 < T_){
            #pragma unroll
            for (int j = 0; j < 8; j++){
                nv[j]  = dblp[(t0+8+j)*48 + lane];
                ndt[j] = dtp[(size_t)(t0+8+j)*DI];
                nu[j]  = up[(size_t)(t0+8+j)*DI];
            }
        }
        // precompute exps + B/C broadcasts (keeps serial h-chain latency-free)
        float dA[8], Bv[8], Cv[8];
        #pragma unroll
        for (int j = 0; j < 8; j++){
            dA[j] = __expf(dtv[j] * A);
            Bv[j] = __shfl_sync(0xffffffffu, v[j], s);
            Cv[j] = __shfl_sync(0xffffffffu, v[j], s + 16);
        }
        #pragma unroll
        for (int j = 0; j < 8; j++){
            h = fmaf(h, dA[j], (dtv[j]*uv[j])*Bv[j]);
            float p = h * Cv[j];
            p += __shfl_xor_sync(0xffffffffu, p, 1);
            p += __shfl_xor_sync(0xffffffffu, p, 2);
            p += __shfl_xor_sync(0xffffffffu, p, 4);
            p += __shfl_xor_sync(0xffffffffu, p, 8);
            if (s == 0) yp[(size_t)(t0+j)*DI] = fmaf(uv[j], Dd, p);
        }
        #pragma unroll
        for (int j = 0; j < 8; j++){ v[j] = nv[j]; dtv[j] = ndt[j]; uv[j] = nu[j]; }
    }
}

// ---------------- masked mean pool over time ----------------
__global__ void k_pool(const int* __restrict__ lengths){
    int b = blockIdx.x, tid = threadIdx.x;
    int len = lengths[b];
    if (len < 1) len = 1;
    const float* p = g_xln + (size_t)b*T_*DM + tid;
    float s = 0.f;
    for (int t = 0; t < len; t++) s += p[(size_t)t*DM];
    g_pool[b*DM + tid] = s / (float)len;
}

// ---------------- classifier head ----------------
__global__ void k_head(const float* __restrict__ c1w, const float* __restrict__ c1b,
                       const float* __restrict__ c2w, const float* __restrict__ c2b,
                       float* __restrict__ out){
    int b = blockIdx.x, tid = threadIdx.x;
    __shared__ float ps[DM];
    __shared__ float z1[DM/2];
    ps[tid]       = g_pool[b*DM + tid];
    ps[tid + 128] = g_pool[b*DM + tid + 128];
    __syncthreads();
    float a = c1b[tid];
    #pragma unroll 4
    for (int k = 0; k < DM; k++) a = fmaf(ps[k], c1w[tid*DM + k], a);
    z1[tid] = silu_f(a);
    __syncthreads();
    if (tid < NCLS){
        float o = c2b[tid];
        #pragma unroll 4
        for (int k = 0; k < 128; k++) o = fmaf(z1[k], c2w[tid*128 + k], o);
        out[b*NCLS + tid] = o;
    }
}

// ---------------- host launch ----------------
extern "C" void kernel_launch(void* const* d_in, const int* in_sizes, int n_in,
                              void* d_out, int out_size){
    const float* x      = (const float*)d_in[0];
    const int*   lens   = (const int*)  d_in[1];
    const float* proj_w = (const float*)d_in[2];
    const float* proj_b = (const float*)d_in[3];
    const float* pln_g  = (const float*)d_in[4];
    const float* pln_b  = (const float*)d_in[5];
    const float* ln_g   = (const float*)d_in[6];
    const float* ln_b   = (const float*)d_in[7];
    const float* in_w   = (const float*)d_in[8];
    const float* conv_w = (const float*)d_in[9];
    const float* conv_b = (const float*)d_in[10];
    const float* xp_w   = (const float*)d_in[11];
    const float* dt_w   = (const float*)d_in[12];
    const float* dt_b   = (const float*)d_in[13];
    const float* A_log  = (const float*)d_in[14];
    const float* Dp     = (const float*)d_in[15];
    const float* out_w  = (const float*)d_in[16];
    const float* pre_g  = (const float*)d_in[17];
    const float* pre_b  = (const float*)d_in[18];
    const float* c1_w   = (const float*)d_in[19];
    const float* c1_b   = (const float*)d_in[20];
    const float* c2_w   = (const float*)d_in[21];
    const float* c2_b   = (const float*)d_in[22];
    float* out = (float*)d_out;

    float *p_xz, *p_h;
    __nv_bfloat16 *p_ah, *p_al, *p_inwh, *p_inwl, *p_outwh, *p_outwl;
    cudaGetSymbolAddress((void**)&p_xz,    g_xz);
    cudaGetSymbolAddress((void**)&p_h,     g_h);
    cudaGetSymbolAddress((void**)&p_ah,    g_ah);
    cudaGetSymbolAddress((void**)&p_al,    g_al);
    cudaGetSymbolAddress((void**)&p_inwh,  g_inwh);
    cudaGetSymbolAddress((void**)&p_inwl,  g_inwl);
    cudaGetSymbolAddress((void**)&p_outwh, g_outwh);
    cudaGetSymbolAddress((void**)&p_outwl, g_outwl);

    k_wsplit<<<2048, 256>>>(in_w, out_w);
    k_inproj<<<NTOK, DM>>>(x, proj_w, proj_b, pln_g, pln_b);

    for (int i = 0; i < NL; i++){
        k_ln2<1><<<NTOK, DM>>>(ln_g + i*DM, ln_b + i*DM);

        dim3 gin(2*DI/64, NTOK/128);       // (16, 64)
        mgemm<0><<<gin, 256>>>(p_ah, p_al,
                               p_inwh + (size_t)i*2*DI*DM, p_inwl + (size_t)i*2*DI*DM,
                               p_xz, NTOK, 2*DI, DM);

        k_conv2<<<NTOK*DI/4/256, 256>>>(conv_w + i*DI*4, conv_b + i*DI);

        k_xpdt2<<<NTOK/16, 256>>>(xp_w + (size_t)i*48*DI,
                                  dt_w + (size_t)i*DI*DR,
                                  dt_b + i*DI);

        k_scan<<<512, 256>>>(A_log + (size_t)i*DI*DS, Dp + i*DI);

        k_gate_split<<<NTOK*DI/256, 256>>>();

        dim3 gout(DM/64, NTOK/128);        // (4, 64)
        mgemm<1><<<gout, 256>>>(p_ah, p_al,
                                p_outwh + (size_t)i*DM*DI, p_outwl + (size_t)i*DM*DI,
                                p_h, NTOK, DM, DI);
    }

    k_ln2<0><<<NTOK, DM>>>(pre_g, pre_b);
    k_pool<<<B_, DM>>>(lens);
    k_head<<<B_, 128>>>(c1_w, c1_b, c2_w, c2_b, out);
}